// round 1
// baseline (speedup 1.0000x reference)
#include <cuda_runtime.h>
#include <math.h>

#define NN 16384
#define DIN 128
#define DX 256
#define DOUT 128
#define BG 32
#define NPER 512
#define KCL 64
#define ACOLS 2048
#define CCOLS 384
#define EMAX 262144
#define ADJ_OFF (2048*2048)

// ---------------- device scratch ----------------
__device__ int   g_deg[NN];
__device__ int   g_off[NN + 1];
__device__ int   g_cur[NN];
__device__ int   g_csr[EMAX];
__device__ float g_X[NN * DX];          // [h | h_neigh], 16 MB
__device__ float g_Wcat[DX * CCOLS];    // [W_feat(128) | M(256)]
__device__ float g_C[NN * CCOLS];       // X @ Wcat
__device__ float g_feat[NN * DOUT];
__device__ float g_rnp[NN];             // 1/max(||pool bundle||, 1e-12)
__device__ float g_s[NN * KCL];         // block-local softmax assignments
__device__ float g_as[NN * KCL];        // A @ S (block-local)
__device__ float g_u[DX];               // W_pool @ b_pool
__device__ float g_cb;                  // ||b_pool||^2

// ---------------- init ----------------
__global__ void k_zero() {
    int i = blockIdx.x * blockDim.x + threadIdx.x;
    int st = gridDim.x * blockDim.x;
    for (int j = i; j < DX * CCOLS; j += st) g_Wcat[j] = 0.f;
    for (int j = i; j < NN; j += st) g_deg[j] = 0;
}

// ---------------- CSR build ----------------
__global__ void k_deg(const int* __restrict__ dst, int E) {
    for (int i = blockIdx.x * blockDim.x + threadIdx.x; i < E;
         i += gridDim.x * blockDim.x)
        atomicAdd(&g_deg[dst[i]], 1);
}

__global__ void k_scan() {  // 1 block, 1024 threads, 16 elems each
    __shared__ int ps[1024];
    int t = threadIdx.x;
    int base = t * 16;
    int loc[16];
    int s = 0;
#pragma unroll
    for (int i = 0; i < 16; i++) { loc[i] = g_deg[base + i]; s += loc[i]; }
    ps[t] = s;
    __syncthreads();
    for (int off = 1; off < 1024; off <<= 1) {
        int v = 0;
        if (t >= off) v = ps[t - off];
        __syncthreads();
        if (t >= off) ps[t] += v;
        __syncthreads();
    }
    int run = (t == 0) ? 0 : ps[t - 1];
#pragma unroll
    for (int i = 0; i < 16; i++) {
        g_off[base + i] = run;
        g_cur[base + i] = run;
        run += loc[i];
    }
    if (t == 1023) g_off[NN] = run;
}

__global__ void k_fill(const int* __restrict__ src, const int* __restrict__ dst, int E) {
    for (int i = blockIdx.x * blockDim.x + threadIdx.x; i < E;
         i += gridDim.x * blockDim.x) {
        int p = atomicAdd(&g_cur[dst[i]], 1);
        g_csr[p] = src[i];
    }
}

// ---------------- neighbor mean + bundle build ----------------
__global__ void k_agg(const float* __restrict__ h) {
    int w = (blockIdx.x * blockDim.x + threadIdx.x) >> 5;
    int l = threadIdx.x & 31;
    if (w >= NN) return;
    int b = g_off[w], e = g_off[w + 1];
    float4 acc = make_float4(0.f, 0.f, 0.f, 0.f);
    for (int t = b; t < e; t++) {
        int s = g_csr[t];
        float4 v = *(const float4*)(h + (size_t)s * DIN + l * 4);
        acc.x += v.x; acc.y += v.y; acc.z += v.z; acc.w += v.w;
    }
    float inv = 1.f / fmaxf((float)(e - b), 1.f);
    float4 own = *(const float4*)(h + (size_t)w * DIN + l * 4);
    *(float4*)(g_X + (size_t)w * DX + l * 4) = own;
    acc.x *= inv; acc.y *= inv; acc.z *= inv; acc.w *= inv;
    *(float4*)(g_X + (size_t)w * DX + DIN + l * 4) = acc;
}

// ---------------- weight preprocessing ----------------
__global__ void k_packWf(const float* __restrict__ Wf) {
    for (int i = blockIdx.x * blockDim.x + threadIdx.x; i < DX * DOUT;
         i += gridDim.x * blockDim.x) {
        int a = i / DOUT, c = i % DOUT;
        g_Wcat[a * CCOLS + c] = Wf[i];
    }
}

__global__ void k_ub(const float* __restrict__ Wp, const float* __restrict__ bp) {
    __shared__ float red[256];
    int a = blockIdx.x;
    float s = 0.f;
    if (a < DX) {
        for (int j = threadIdx.x; j < ACOLS; j += blockDim.x)
            s += Wp[(size_t)a * ACOLS + j] * bp[j];
    } else {
        for (int j = threadIdx.x; j < ACOLS; j += blockDim.x) {
            float b = bp[j]; s += b * b;
        }
    }
    red[threadIdx.x] = s;
    __syncthreads();
    for (int o = 128; o > 0; o >>= 1) {
        if (threadIdx.x < o) red[threadIdx.x] += red[threadIdx.x + o];
        __syncthreads();
    }
    if (threadIdx.x == 0) {
        if (a < DX) g_u[a] = red[0];
        else g_cb = red[0];
    }
}

// M = W_pool @ W_pool^T, split-K with atomic accumulation into g_Wcat[:,128:384]
__global__ void k_M(const float* __restrict__ Wp) {
    __shared__ float Sa[64][65];
    __shared__ float Sb[64][65];
    int a0 = blockIdx.x * 64, b0 = blockIdx.y * 64, k0 = blockIdx.z * 256;
    int tid = threadIdx.x;
    int tx = tid & 15, ty = tid >> 4;
    float acc[4][4] = {};
    for (int kk = k0; kk < k0 + 256; kk += 64) {
#pragma unroll
        for (int q = 0; q < 16; q++) {
            int idx = tid + q * 256;
            int r = idx >> 6, c = idx & 63;
            Sa[r][c] = Wp[(size_t)(a0 + r) * ACOLS + kk + c];
            Sb[r][c] = Wp[(size_t)(b0 + r) * ACOLS + kk + c];
        }
        __syncthreads();
        for (int k = 0; k < 64; k++) {
            float ra[4], rb[4];
#pragma unroll
            for (int i = 0; i < 4; i++) { ra[i] = Sa[ty * 4 + i][k]; rb[i] = Sb[tx * 4 + i][k]; }
#pragma unroll
            for (int i = 0; i < 4; i++)
#pragma unroll
                for (int j = 0; j < 4; j++) acc[i][j] += ra[i] * rb[j];
        }
        __syncthreads();
    }
#pragma unroll
    for (int i = 0; i < 4; i++)
#pragma unroll
        for (int j = 0; j < 4; j++)
            atomicAdd(&g_Wcat[(a0 + ty * 4 + i) * CCOLS + 128 + b0 + tx * 4 + j],
                      acc[i][j]);
}

// ---------------- main GEMM: C[16384,384] = X[16384,256] @ Wcat[256,384] ----------------
__global__ void k_gemm() {
    __shared__ float As[16][132];  // [k][m]
    __shared__ float Bs[16][128];  // [k][n]
    int n0 = blockIdx.x * 128;
    int m0 = blockIdx.y * 128;
    int tid = threadIdx.x;
    int tx = tid & 15, ty = tid >> 4;
    float acc[8][8] = {};
    for (int k0 = 0; k0 < DX; k0 += 16) {
#pragma unroll
        for (int q = 0; q < 2; q++) {
            int idx = tid + q * 256;  // 0..511
            int r = idx >> 2, k4 = (idx & 3) * 4;
            float4 v = *(const float4*)(g_X + (size_t)(m0 + r) * DX + k0 + k4);
            As[k4 + 0][r] = v.x; As[k4 + 1][r] = v.y;
            As[k4 + 2][r] = v.z; As[k4 + 3][r] = v.w;
            int k = idx >> 5, n4 = (idx & 31) * 4;
            *(float4*)(&Bs[k][n4]) =
                *(const float4*)(g_Wcat + (size_t)(k0 + k) * CCOLS + n0 + n4);
        }
        __syncthreads();
#pragma unroll
        for (int kk = 0; kk < 16; kk++) {
            float4 a0v = *(float4*)(&As[kk][ty * 4]);
            float4 a1v = *(float4*)(&As[kk][64 + ty * 4]);
            float4 b0v = *(float4*)(&Bs[kk][tx * 4]);
            float4 b1v = *(float4*)(&Bs[kk][64 + tx * 4]);
            float ra[8] = {a0v.x, a0v.y, a0v.z, a0v.w, a1v.x, a1v.y, a1v.z, a1v.w};
            float rb[8] = {b0v.x, b0v.y, b0v.z, b0v.w, b1v.x, b1v.y, b1v.z, b1v.w};
#pragma unroll
            for (int i = 0; i < 8; i++)
#pragma unroll
                for (int j = 0; j < 8; j++) acc[i][j] += ra[i] * rb[j];
        }
        __syncthreads();
    }
#pragma unroll
    for (int i = 0; i < 8; i++) {
        int row = m0 + ((i < 4) ? (ty * 4 + i) : (64 + ty * 4 + i - 4));
#pragma unroll
        for (int jh = 0; jh < 2; jh++) {
            int col = n0 + jh * 64 + tx * 4;
            float4 v = make_float4(acc[i][jh * 4 + 0], acc[i][jh * 4 + 1],
                                   acc[i][jh * 4 + 2], acc[i][jh * 4 + 3]);
            *(float4*)(g_C + (size_t)row * CCOLS + col) = v;
        }
    }
}

// ---------------- post: feat normalize+relu, pool norm reciprocal ----------------
__global__ void k_post(const float* __restrict__ bfeat) {
    int w = (blockIdx.x * blockDim.x + threadIdx.x) >> 5;
    int l = threadIdx.x & 31;
    if (w >= NN) return;
    const float* Crow = g_C + (size_t)w * CCOLS;
    const float* Xrow = g_X + (size_t)w * DX;
    float q = 0.f, xu = 0.f;
#pragma unroll
    for (int r = 0; r < 8; r++) {
        int j = l + 32 * r;
        float x = Xrow[j];
        q += x * Crow[128 + j];
        xu += x * g_u[j];
    }
#pragma unroll
    for (int o = 16; o > 0; o >>= 1) {
        q += __shfl_xor_sync(0xffffffffu, q, o);
        xu += __shfl_xor_sync(0xffffffffu, xu, o);
    }
    float n2 = q + 2.f * xu + g_cb;
    float rn = 1.f / fmaxf(sqrtf(fmaxf(n2, 0.f)), 1e-12f);
    if (l == 0) g_rnp[w] = rn;

    float f[4];
    float s2 = 0.f;
#pragma unroll
    for (int r = 0; r < 4; r++) {
        int j = l + 32 * r;
        f[r] = Crow[j] + bfeat[j];
        s2 += f[r] * f[r];
    }
#pragma unroll
    for (int o = 16; o > 0; o >>= 1) s2 += __shfl_xor_sync(0xffffffffu, s2, o);
    float rf = 1.f / fmaxf(sqrtf(s2), 1e-12f);
#pragma unroll
    for (int r = 0; r < 4; r++)
        g_feat[(size_t)w * DOUT + l + 32 * r] = fmaxf(f[r] * rf, 0.f);
}

// ---------------- per-graph assign GEMM + in-graph softmax ----------------
__global__ void k_assign(const float* __restrict__ Wp, const float* __restrict__ bp) {
    __shared__ float smem_buf[64 * 68 + 64 * 64];
    float(*Xs)[68] = (float(*)[68])smem_buf;                 // [row][k]
    float(*Ws)[64] = (float(*)[64])(smem_buf + 64 * 68);     // [k][col]
    float(*Zs)[65] = (float(*)[65])smem_buf;                 // aliases Xs after GEMM

    int g = blockIdx.y;
    int n0 = g * NPER + blockIdx.x * 64;
    int tid = threadIdx.x;
    int tx = tid & 15, ty = tid >> 4;
    float acc[4][4] = {};
    for (int k0 = 0; k0 < DX; k0 += 64) {
#pragma unroll
        for (int q = 0; q < 16; q++) {
            int idx = tid + q * 256;
            int r = idx >> 6, c = idx & 63;
            Xs[r][c] = g_X[(size_t)(n0 + r) * DX + k0 + c];
            Ws[r][c] = Wp[(size_t)(k0 + r) * ACOLS + g * KCL + c];
        }
        __syncthreads();
        for (int k = 0; k < 64; k++) {
            float ra[4];
#pragma unroll
            for (int i = 0; i < 4; i++) ra[i] = Xs[ty * 4 + i][k];
            float4 b4 = *(float4*)(&Ws[k][tx * 4]);
            float rb[4] = {b4.x, b4.y, b4.z, b4.w};
#pragma unroll
            for (int i = 0; i < 4; i++)
#pragma unroll
                for (int j = 0; j < 4; j++) acc[i][j] += ra[i] * rb[j];
        }
        __syncthreads();
    }
#pragma unroll
    for (int i = 0; i < 4; i++)
#pragma unroll
        for (int j = 0; j < 4; j++) Zs[ty * 4 + i][tx * 4 + j] = acc[i][j];
    __syncthreads();

    int wid = tid >> 5, l = tid & 31;
    for (int rr = 0; rr < 8; rr++) {
        int row = wid * 8 + rr;
        int node = n0 + row;
        float rn = g_rnp[node];
        float v0 = fmaxf((Zs[row][l] + bp[g * KCL + l]) * rn, 0.f);
        float v1 = fmaxf((Zs[row][l + 32] + bp[g * KCL + l + 32]) * rn, 0.f);
        float e0 = expf(v0), e1 = expf(v1);
        float t = e0 + e1;
#pragma unroll
        for (int o = 16; o > 0; o >>= 1) t += __shfl_xor_sync(0xffffffffu, t, o);
        float inv = 1.f / t;
        g_s[(size_t)node * KCL + l] = e0 * inv;
        g_s[(size_t)node * KCL + l + 32] = e1 * inv;
    }
}

// ---------------- a_s = A @ S (CSR gather over edges) ----------------
__global__ void k_as() {
    int w = (blockIdx.x * blockDim.x + threadIdx.x) >> 5;
    int l = threadIdx.x & 31;
    if (w >= NN) return;
    int b = g_off[w], e = g_off[w + 1];
    float a0 = 0.f, a1 = 0.f;
    for (int t = b; t < e; t++) {
        int s = g_csr[t];
        a0 += g_s[(size_t)s * KCL + l];
        a1 += g_s[(size_t)s * KCL + 32 + l];
    }
    g_as[(size_t)w * KCL + l] = a0;
    g_as[(size_t)w * KCL + 32 + l] = a1;
}

// ---------------- h_new blocks: S_g^T @ feat_g (split-K, atomics) ----------------
__global__ void k_hnew(float* __restrict__ out) {
    __shared__ float Ss[64][64];    // [node][cluster]
    __shared__ float Ff[64][128];   // [node][dim]
    int g = blockIdx.y;
    int n0 = g * NPER + blockIdx.x * 64;
    int tid = threadIdx.x;
    int tx = tid & 31, ty = tid >> 5;
#pragma unroll
    for (int q = 0; q < 16; q++) {
        int idx = tid + q * 256;
        Ss[idx >> 6][idx & 63] = g_s[(size_t)(n0 + (idx >> 6)) * KCL + (idx & 63)];
    }
#pragma unroll
    for (int q = 0; q < 32; q++) {
        int idx = tid + q * 256;
        Ff[idx >> 7][idx & 127] = g_feat[(size_t)(n0 + (idx >> 7)) * DOUT + (idx & 127)];
    }
    __syncthreads();
    float acc[8][4] = {};
    for (int k = 0; k < 64; k++) {
        float4 f4 = *(float4*)(&Ff[k][tx * 4]);
#pragma unroll
        for (int r = 0; r < 8; r++) {
            float a = Ss[k][ty * 8 + r];
            acc[r][0] += a * f4.x; acc[r][1] += a * f4.y;
            acc[r][2] += a * f4.z; acc[r][3] += a * f4.w;
        }
    }
#pragma unroll
    for (int r = 0; r < 8; r++) {
        size_t base = (size_t)ADJ_OFF + (size_t)(g * KCL + ty * 8 + r) * DOUT + tx * 4;
#pragma unroll
        for (int j = 0; j < 4; j++) atomicAdd(out + base + j, acc[r][j]);
    }
}

// ---------------- adj blocks: S_g^T @ (A S)_g (split-K, atomics) ----------------
__global__ void k_adj(float* __restrict__ out) {
    __shared__ float Ss[64][64];
    __shared__ float Aa[64][64];
    int g = blockIdx.y;
    int n0 = g * NPER + blockIdx.x * 64;
    int tid = threadIdx.x;
    int tx = tid & 15, ty = tid >> 4;
#pragma unroll
    for (int q = 0; q < 16; q++) {
        int idx = tid + q * 256;
        int r = idx >> 6, c = idx & 63;
        Ss[r][c] = g_s[(size_t)(n0 + r) * KCL + c];
        Aa[r][c] = g_as[(size_t)(n0 + r) * KCL + c];
    }
    __syncthreads();
    float acc[4][4] = {};
    for (int k = 0; k < 64; k++) {
        float ra[4];
#pragma unroll
        for (int i = 0; i < 4; i++) ra[i] = Ss[k][ty * 4 + i];
        float4 b4 = *(float4*)(&Aa[k][tx * 4]);
        float rb[4] = {b4.x, b4.y, b4.z, b4.w};
#pragma unroll
        for (int i = 0; i < 4; i++)
#pragma unroll
            for (int j = 0; j < 4; j++) acc[i][j] += ra[i] * rb[j];
    }
#pragma unroll
    for (int i = 0; i < 4; i++) {
        size_t base = (size_t)(g * KCL + ty * 4 + i) * 2048 + g * KCL + tx * 4;
#pragma unroll
        for (int j = 0; j < 4; j++) atomicAdd(out + base + j, acc[i][j]);
    }
}

// ---------------- launch ----------------
extern "C" void kernel_launch(void* const* d_in, const int* in_sizes, int n_in,
                              void* d_out, int out_size) {
    const float* h  = (const float*)d_in[0];
    const float* Wf = (const float*)d_in[1];
    const float* bf = (const float*)d_in[2];
    const float* Wp = (const float*)d_in[3];
    const float* bp = (const float*)d_in[4];
    const int* esrc = (const int*)d_in[5];
    const int* edst = (const int*)d_in[6];
    int E = in_sizes[5];
    float* out = (float*)d_out;

    cudaMemsetAsync(d_out, 0, (size_t)out_size * sizeof(float));
    k_zero<<<256, 256>>>();
    k_deg<<<512, 256>>>(edst, E);
    k_scan<<<1, 1024>>>();
    k_fill<<<512, 256>>>(esrc, edst, E);
    k_agg<<<2048, 256>>>(h);
    k_packWf<<<128, 256>>>(Wf);
    k_ub<<<257, 256>>>(Wp, bp);
    k_M<<<dim3(4, 4, 8), 256>>>(Wp);
    k_gemm<<<dim3(3, 128), 256>>>();
    k_post<<<2048, 256>>>(bf);
    k_assign<<<dim3(8, BG), 256>>>(Wp, bp);
    k_as<<<2048, 256>>>();
    k_hnew<<<dim3(8, BG), 256>>>(out);
    k_adj<<<dim3(8, BG), 256>>>(out);
}